// round 9
// baseline (speedup 1.0000x reference)
#include <cuda_runtime.h>
#include <cuda_fp16.h>
#include <cstdint>

// ============================================================================
// PairwiseMLPLinkPredictor — persistent HMMA with fragment double-buffering.
//   1 CTA/SM, 512 threads, ALL 16 warps compute every phase.
//   W1 [256n][256k] fp16 swizzled RESIDENT in smem (131KB).
//   W2 held in REGISTERS as mma B-fragments (32 regs/lane, loaded once).
//   feats double buffer 2 x [64 pairs][256] fp16 (32KB each).
//   Inner loops prefetch next-ks fragments -> LDSM latency hidden.
// ============================================================================

#define NTH   512
#define TILE  64

// ---- SMEM layout (bytes) ----
#define OFF_W1   0         // 131072
#define OFF_F0   131072    // 32768
#define OFF_F1   163840    // 32768
#define OFF_B1   196608    // 1024
#define OFF_PART 197632    // 4096 : [16 warps][64 rows]
#define SMEM_BYTES 201728

// swizzled offset in a [rows][256] fp16 tile (512B rows, 32 chunks of 16B)
__host__ __device__ __forceinline__ uint32_t timg(int r, int k) {
    return (uint32_t)(r * 512 + ((((k >> 3) ^ (r & 7)) & 31) << 4) + ((k & 7) << 1));
}

// ---- global fp16 weight images (prep kernel output; both layouts validated) --
__device__ __align__(1024) unsigned char g_W1h[131072];  // [256][256] swizzled
__device__ __align__(1024) unsigned char g_W2t[65536];   // [128 n][256 k] plain

// ---------------------------------------------------------------------------
__device__ __forceinline__ uint32_t smem_u32(const void* p) {
    uint32_t a;
    asm("{ .reg .u64 t; cvta.to.shared.u64 t, %1; cvt.u32.u64 %0, t; }" : "=r"(a) : "l"(p));
    return a;
}
__device__ __forceinline__ void ldsm_x4(uint32_t r[4], uint32_t addr) {
    asm volatile("ldmatrix.sync.aligned.m8n8.x4.shared.b16 {%0,%1,%2,%3}, [%4];"
                 : "=r"(r[0]), "=r"(r[1]), "=r"(r[2]), "=r"(r[3]) : "r"(addr));
}
__device__ __forceinline__ void mma16816(float c[4], const uint32_t a[4],
                                         uint32_t b0, uint32_t b1) {
    asm volatile("mma.sync.aligned.m16n8k16.row.col.f32.f16.f16.f32 "
                 "{%0,%1,%2,%3}, {%4,%5,%6,%7}, {%8,%9}, {%0,%1,%2,%3};"
                 : "+f"(c[0]), "+f"(c[1]), "+f"(c[2]), "+f"(c[3])
                 : "r"(a[0]), "r"(a[1]), "r"(a[2]), "r"(a[3]), "r"(b0), "r"(b1));
}
#define CP16(dst, src) \
    asm volatile("cp.async.cg.shared.global [%0], [%1], 16;" :: "r"(dst), "l"(src) : "memory")
#define CP_COMMIT() asm volatile("cp.async.commit_group;" ::: "memory")
#define CP_WAIT0()  asm volatile("cp.async.wait_group 0;" ::: "memory")

// ---------------------------------------------------------------------------
// Prep: W1h[n][k] = fp16(W1[k*256+n]) swizzled; W2t[n][k] = fp16(W2[k*128+n]).
// ---------------------------------------------------------------------------
__global__ void prep_kernel(const float* __restrict__ W1, const float* __restrict__ W2) {
    const int i = blockIdx.x * blockDim.x + threadIdx.x;  // 65536
    {
        const int n = i >> 8, k = i & 255;
        *(__half*)(g_W1h + timg(n, k)) = __float2half(W1[k * 256 + n]);
    }
    if (i < 32768) {
        const int n = i >> 8, k = i & 255;
        ((__half*)g_W2t)[n * 256 + k] = __float2half(W2[k * 128 + n]);
    }
}

// ---------------------------------------------------------------------------
__device__ __forceinline__ void gather_tile(char* smem, uint32_t bufOff,
                                            const float* __restrict__ x,
                                            const void* __restrict__ ep, bool is32,
                                            long long e0, int E, int tid)
{
    const int p = tid >> 3, sub = tid & 7;
    const long long e = e0 + p;
    long long ia = 0, ib = 0;
    if (e < (long long)E) {
        if (is32) { ia = ((const int*)ep)[2 * e];       ib = ((const int*)ep)[2 * e + 1]; }
        else      { ia = ((const long long*)ep)[2 * e]; ib = ((const long long*)ep)[2 * e + 1]; }
    }
    const float* xa = x + (size_t)ia * 256;
    const float* xb = x + (size_t)ib * 256;
    const int k0 = sub * 32;
    #pragma unroll
    for (int j = 0; j < 4; j++) {
        const int k = k0 + 8 * j;
        float4 a0 = __ldg((const float4*)(xa + k));
        float4 a1 = __ldg((const float4*)(xa + k + 4));
        float4 c0 = __ldg((const float4*)(xb + k));
        float4 c1 = __ldg((const float4*)(xb + k + 4));
        union { __half2 h; uint32_t u; } q0, q1, q2, q3;
        q0.h = __floats2half2_rn(a0.x * c0.x, a0.y * c0.y);
        q1.h = __floats2half2_rn(a0.z * c0.z, a0.w * c0.w);
        q2.h = __floats2half2_rn(a1.x * c1.x, a1.y * c1.y);
        q3.h = __floats2half2_rn(a1.z * c1.z, a1.w * c1.w);
        *(uint4*)(smem + bufOff + timg(p, k)) = make_uint4(q0.u, q1.u, q2.u, q3.u);
    }
}

// ---------------------------------------------------------------------------
__global__ void __launch_bounds__(NTH, 1)
pairmlp_pf_kernel(const float* __restrict__ x,
                  const float* __restrict__ b1, const float* __restrict__ b2,
                  const float* __restrict__ W3, const float* __restrict__ b3,
                  const void*  __restrict__ ep, float* __restrict__ out,
                  int E, int T)
{
    extern __shared__ char smem[];
    const uint32_t sb = smem_u32(smem);
    const int tid = threadIdx.x, w = tid >> 5, lane = tid & 31;
    const int g = lane >> 2, tig = lane & 3;

    float* sB1 = (float*)(smem + OFF_B1);
    float* sPart = (float*)(smem + OFF_PART);

    // ---- dtype probe: int64 edge_pairs -> odd int32 words of first 1KB all 0 ----
    int probe = 0;
    if (tid < 128) probe = ((const int*)ep)[2 * tid + 1];
    const bool is32 = (__syncthreads_or(probe != 0) != 0);

    // ---- W1 image -> SMEM once (cp.async 128KB) ----
    #pragma unroll
    for (int i = 0; i < 16; i++) {
        const int c = tid + i * NTH;
        CP16(sb + OFF_W1 + c * 16, g_W1h + c * 16);
    }
    CP_COMMIT();

    // ---- W2 B-fragments -> registers once (validated R5 path) ----
    uint32_t w2f[32];
    {
        const uint32_t* w2t = (const uint32_t*)g_W2t;   // half2 units, row stride 128
        const int n2 = w * 8 + (lane >> 2);
        #pragma unroll
        for (int ks = 0; ks < 16; ks++) {
            w2f[2 * ks]     = w2t[n2 * 128 + 8 * ks + tig];
            w2f[2 * ks + 1] = w2t[n2 * 128 + 8 * ks + 4 + tig];
        }
    }
    float2 b2v, w3v;
    {
        const int n0 = w * 8 + 2 * tig;
        b2v = *(const float2*)&b2[n0];
        w3v = *(const float2*)&W3[n0];
    }
    const float b3v = __ldg(b3);
    if (tid < 256) sB1[tid] = b1[tid];

    // ---- first tile -> F0 ----
    if (blockIdx.x < (unsigned)T)
        gather_tile(smem, OFF_F0, x, ep, is32, (long long)blockIdx.x * TILE, E, tid);
    CP_WAIT0();
    __syncthreads();

    // warp geometry
    const int wm = w & 1, wn = w >> 1;                      // L1: 2m x 8n (32x32)
    const int arow0 = ((lane >> 3) & 1) * 8 + (lane & 7);
    const int acsel = lane >> 4;
    const int brow0 = ((lane >> 4) & 1) * 8 + (lane & 7);
    const int bcsel = (lane >> 3) & 1;

    int cur = 0;
    for (int tile = blockIdx.x; tile < T; tile += gridDim.x) {
        const uint32_t fOff = cur ? OFF_F1 : OFF_F0;
        const uint32_t aB = sb + fOff;
        const long long e0 = (long long)tile * TILE;

        // ================ layer 1: 64x256x256, warp 32x32, prefetched ========
        float acc1[2][4][4];
        #pragma unroll
        for (int mi = 0; mi < 2; mi++)
            #pragma unroll
            for (int ni = 0; ni < 4; ni++)
                #pragma unroll
                for (int v = 0; v < 4; v++) acc1[mi][ni][v] = 0.0f;

        uint32_t afr[2][2][4], bfr[2][2][4];
        #define L1_LOAD(S, KS) do {                                              \
            _Pragma("unroll")                                                    \
            for (int mi = 0; mi < 2; mi++) {                                     \
                const int r = wm * 32 + mi * 16 + arow0;                         \
                ldsm_x4(afr[S][mi],                                              \
                        aB + r * 512 + ((((2*(KS) + acsel) ^ (r & 7)) & 31) << 4)); \
            }                                                                    \
            _Pragma("unroll")                                                    \
            for (int nb = 0; nb < 2; nb++) {                                     \
                const int r = wn * 32 + nb * 16 + brow0;                         \
                ldsm_x4(bfr[S][nb],                                              \
                        sb + OFF_W1 + r * 512 + ((((2*(KS) + bcsel) ^ (r & 7)) & 31) << 4)); \
            } } while (0)

        L1_LOAD(0, 0);
        #pragma unroll
        for (int ks = 0; ks < 16; ks++) {
            const int cs = ks & 1, nsl = cs ^ 1;
            if (ks < 15) L1_LOAD(nsl, ks + 1);
            #pragma unroll
            for (int nb = 0; nb < 2; nb++)
                #pragma unroll
                for (int mi = 0; mi < 2; mi++) {
                    mma16816(acc1[mi][nb * 2 + 0], afr[cs][mi], bfr[cs][nb][0], bfr[cs][nb][1]);
                    mma16816(acc1[mi][nb * 2 + 1], afr[cs][mi], bfr[cs][nb][2], bfr[cs][nb][3]);
                }
        }
        #undef L1_LOAD
        __syncthreads();     // feats(t) fully consumed

        // ---- epilogue 1: h1 = fp16(relu(acc1 + b1)) -> same buffer ----
        #pragma unroll
        for (int mi = 0; mi < 2; mi++) {
            const int r0 = wm * 32 + mi * 16 + g, r1 = r0 + 8;
            #pragma unroll
            for (int ni = 0; ni < 4; ni++) {
                const int c0 = wn * 32 + ni * 8 + 2 * tig;
                const float2 bb = *(const float2*)&sB1[c0];
                union { __half2 h; uint32_t u; } lo, hi;
                lo.h = __floats2half2_rn(fmaxf(acc1[mi][ni][0] + bb.x, 0.0f),
                                         fmaxf(acc1[mi][ni][1] + bb.y, 0.0f));
                hi.h = __floats2half2_rn(fmaxf(acc1[mi][ni][2] + bb.x, 0.0f),
                                         fmaxf(acc1[mi][ni][3] + bb.y, 0.0f));
                *(uint32_t*)(smem + fOff + timg(r0, c0)) = lo.u;
                *(uint32_t*)(smem + fOff + timg(r1, c0)) = hi.u;
            }
        }
        // ---- gather(t+grid) into other buffer ----
        {
            const int nxt = tile + gridDim.x;
            if (nxt < T)
                gather_tile(smem, cur ? OFF_F0 : OFF_F1, x, ep, is32,
                            (long long)nxt * TILE, E, tid);
        }
        __syncthreads();     // h1 visible (and next feats staged)

        // ================ layer 2: 64x128x256, warp 64x8, B in regs ==========
        float acc2[4][4];
        #pragma unroll
        for (int mt = 0; mt < 4; mt++)
            #pragma unroll
            for (int v = 0; v < 4; v++) acc2[mt][v] = 0.0f;

        uint32_t af2[2][4][4];
        #define L2_LOAD(S, KS) do {                                              \
            _Pragma("unroll")                                                    \
            for (int mt = 0; mt < 4; mt++) {                                     \
                const int r = mt * 16 + arow0;                                   \
                ldsm_x4(af2[S][mt],                                              \
                        aB + r * 512 + ((((2*(KS) + acsel) ^ (r & 7)) & 31) << 4)); \
            } } while (0)

        L2_LOAD(0, 0);
        #pragma unroll
        for (int ks = 0; ks < 16; ks++) {
            const int cs = ks & 1, nsl = cs ^ 1;
            if (ks < 15) L2_LOAD(nsl, ks + 1);
            #pragma unroll
            for (int mt = 0; mt < 4; mt++)
                mma16816(acc2[mt], af2[cs][mt], w2f[2 * ks], w2f[2 * ks + 1]);
        }
        #undef L2_LOAD

        // ---- layer 3: reduce + store ----
        #pragma unroll
        for (int mt = 0; mt < 4; mt++) {
            float s0 = fmaxf(acc2[mt][0] + b2v.x, 0.0f) * w3v.x
                     + fmaxf(acc2[mt][1] + b2v.y, 0.0f) * w3v.y;
            float s1 = fmaxf(acc2[mt][2] + b2v.x, 0.0f) * w3v.x
                     + fmaxf(acc2[mt][3] + b2v.y, 0.0f) * w3v.y;
            s0 += __shfl_xor_sync(0xffffffffu, s0, 1);
            s0 += __shfl_xor_sync(0xffffffffu, s0, 2);
            s1 += __shfl_xor_sync(0xffffffffu, s1, 1);
            s1 += __shfl_xor_sync(0xffffffffu, s1, 2);
            if (tig == 0) {
                sPart[w * 64 + mt * 16 + g]     = s0;
                sPart[w * 64 + mt * 16 + 8 + g] = s1;
            }
        }
        __syncthreads();
        if (tid < 64) {
            const long long e = e0 + tid;
            if (e < E) {
                float s = b3v;
                #pragma unroll
                for (int ww = 0; ww < 16; ww++) s += sPart[ww * 64 + tid];
                out[e] = s;
            }
        }
        __syncthreads();     // sPart + buffers free
        cur ^= 1;
    }
}

// ---------------------------------------------------------------------------
extern "C" void kernel_launch(void* const* d_in, const int* in_sizes, int n_in,
                              void* d_out, int out_size)
{
    const float* x  = (const float*)d_in[0];
    const float* W1 = (const float*)d_in[1];
    const float* b1 = (const float*)d_in[2];
    const float* W2 = (const float*)d_in[3];
    const float* b2 = (const float*)d_in[4];
    const float* W3 = (const float*)d_in[5];
    const float* b3 = (const float*)d_in[6];
    // d_in[7] = edge_index (unused)
    const void*  ep = d_in[8];
    float* out = (float*)d_out;

    const int E = out_size;
    const int T = (E + TILE - 1) / TILE;

    prep_kernel<<<256, 256>>>(W1, W2);

    int dev = 0, sms = 148;
    cudaGetDevice(&dev);
    cudaDeviceGetAttribute(&sms, cudaDevAttrMultiProcessorCount, dev);
    const int grid = sms < T ? sms : T;

    cudaFuncSetAttribute(pairmlp_pf_kernel,
                         cudaFuncAttributeMaxDynamicSharedMemorySize, SMEM_BYTES);
    pairmlp_pf_kernel<<<grid, NTH, SMEM_BYTES>>>(x, b1, b2, W3, b3, ep, out, E, T);
}

// round 10
// speedup vs baseline: 1.3160x; 1.3160x over previous
#include <cuda_runtime.h>
#include <cuda_fp16.h>
#include <cstdint>

// ============================================================================
// PairwiseMLPLinkPredictor — 64-register HMMA kernel, 32 warps/SM.
//   2 CTAs/SM x 512 threads. TILE=64 pairs/CTA, non-persistent grid.
//   W1 streamed as 8 x 16KB slices [256n][32k] (64B-row swizzle).
//   W2 streamed as 4 x 16KB slices [128n][64k] (128B-row swizzle, R6 layout).
//   L1 warp tile 32x32 (acc 32 regs), L2 warp tile 32x16 (acc 16 regs).
// ============================================================================

#define NTH    512
#define TILE   64

// ---- SMEM layout (bytes), 68608 per CTA -> 2 CTAs/SM ----
#define OFF_F     0        // 32768 : feats/h1 [64][256] f16 swizzled (512B rows)
#define OFF_WS0   32768    // 16384 : weight slice buffer 0
#define OFF_WS1   49152    // 16384 : weight slice buffer 1
#define OFF_B1    65536    // 1024
#define OFF_PART  66560    // 2048  : [8 ngroups][64 rows]
#define SMEM_BYTES 68608

// feats tile [rows][256] f16, 512B rows, 32 x 16B chunks, XOR-(r&7) swizzle
__host__ __device__ __forceinline__ uint32_t timg(int r, int k) {
    return (uint32_t)(r * 512 + ((((k >> 3) ^ (r & 7)) & 31) << 4) + ((k & 7) << 1));
}
// W1 slice [256n][32k] f16, 64B rows, 4 x 16B chunks, XOR-((r>>1)&3) swizzle
__host__ __device__ __forceinline__ uint32_t sw1(int r, int k) {
    return (uint32_t)(r * 64 + ((((k >> 3) ^ ((r >> 1) & 3)) & 3) << 4) + ((k & 7) << 1));
}
// W2 slice [128n][64k] f16, 128B rows, 8 x 16B chunks, XOR-(r&7) swizzle
__host__ __device__ __forceinline__ uint32_t sw2(int r, int k) {
    return (uint32_t)(r * 128 + ((((k >> 3) ^ (r & 7)) & 7) << 4) + ((k & 7) << 1));
}

// ---- global fp16 weight slice images (prep kernel output) ----
__device__ __align__(1024) unsigned char g_W1s[131072]; // 8 slices [256n][32k]
__device__ __align__(1024) unsigned char g_W2s[65536];  // 4 slices [128n][64k]

// ---------------------------------------------------------------------------
__device__ __forceinline__ uint32_t smem_u32(const void* p) {
    uint32_t a;
    asm("{ .reg .u64 t; cvta.to.shared.u64 t, %1; cvt.u32.u64 %0, t; }" : "=r"(a) : "l"(p));
    return a;
}
__device__ __forceinline__ void ldsm_x4(uint32_t r[4], uint32_t addr) {
    asm volatile("ldmatrix.sync.aligned.m8n8.x4.shared.b16 {%0,%1,%2,%3}, [%4];"
                 : "=r"(r[0]), "=r"(r[1]), "=r"(r[2]), "=r"(r[3]) : "r"(addr));
}
__device__ __forceinline__ void mma16816(float c[4], const uint32_t a[4],
                                         uint32_t b0, uint32_t b1) {
    asm volatile("mma.sync.aligned.m16n8k16.row.col.f32.f16.f16.f32 "
                 "{%0,%1,%2,%3}, {%4,%5,%6,%7}, {%8,%9}, {%0,%1,%2,%3};"
                 : "+f"(c[0]), "+f"(c[1]), "+f"(c[2]), "+f"(c[3])
                 : "r"(a[0]), "r"(a[1]), "r"(a[2]), "r"(a[3]), "r"(b0), "r"(b1));
}
#define CP16(dst, src) \
    asm volatile("cp.async.cg.shared.global [%0], [%1], 16;" :: "r"(dst), "l"(src) : "memory")
#define CP_COMMIT() asm volatile("cp.async.commit_group;" ::: "memory")
#define CP_WAIT(n)  asm volatile("cp.async.wait_group %0;" :: "n"(n) : "memory")

// ---------------------------------------------------------------------------
// Prep: slice + transpose + fp16 + swizzle.
//   W1s[s][n][kk] = fp16(W1[(32s+kk)*256 + n]),  s<8, kk<32
//   W2s[s][n][kk] = fp16(W2[(64s+kk)*128 + n]),  s<4, kk<64
// ---------------------------------------------------------------------------
__global__ void prep_kernel(const float* __restrict__ W1, const float* __restrict__ W2) {
    const int i = blockIdx.x * blockDim.x + threadIdx.x;  // 65536
    {
        const int n = i >> 8, k = i & 255;
        *(__half*)(g_W1s + (k >> 5) * 16384 + sw1(n, k & 31)) =
            __float2half(W1[k * 256 + n]);
    }
    if (i < 32768) {
        const int n = i >> 8, k = i & 255;      // n<128
        *(__half*)(g_W2s + (k >> 6) * 16384 + sw2(n, k & 63)) =
            __float2half(W2[k * 128 + n]);
    }
}

// ---------------------------------------------------------------------------
__global__ void __launch_bounds__(NTH, 2)
pairmlp_occ_kernel(const float* __restrict__ x,
                   const float* __restrict__ b1, const float* __restrict__ b2,
                   const float* __restrict__ W3, const float* __restrict__ b3,
                   const void*  __restrict__ ep, float* __restrict__ out, int E)
{
    extern __shared__ char smem[];
    const uint32_t sb = smem_u32(smem);
    const int tid = threadIdx.x, w = tid >> 5, lane = tid & 31;
    const int g = lane >> 2, tig = lane & 3;
    const long long e0 = (long long)blockIdx.x * TILE;

    float* sB1 = (float*)(smem + OFF_B1);
    float* sPart = (float*)(smem + OFF_PART);

    // ---- dtype probe: int64 edge_pairs -> odd int32 words of first 1KB all 0 ----
    int probe = 0;
    if (tid < 128) probe = ((const int*)ep)[2 * tid + 1];
    const bool is32 = (__syncthreads_or(probe != 0) != 0);

    // ---- kick W1 slice0 -> WS0, slice1 -> WS1 (1024 chunks each) ----
    CP16(sb + OFF_WS0 + tid * 16, g_W1s + tid * 16);
    CP16(sb + OFF_WS0 + (tid + 512) * 16, g_W1s + (tid + 512) * 16);
    CP_COMMIT();
    CP16(sb + OFF_WS1 + tid * 16, g_W1s + 16384 + tid * 16);
    CP16(sb + OFF_WS1 + (tid + 512) * 16, g_W1s + 16384 + (tid + 512) * 16);
    CP_COMMIT();

    if (tid < 256) sB1[tid] = b1[tid];

    // ---- gather + product -> fp16 feats (8 threads per pair) ----
    {
        const int p = tid >> 3, sub = tid & 7;
        const long long e = e0 + p;
        long long ia = 0, ib = 0;
        if (e < (long long)E) {
            if (is32) { ia = ((const int*)ep)[2 * e];       ib = ((const int*)ep)[2 * e + 1]; }
            else      { ia = ((const long long*)ep)[2 * e]; ib = ((const long long*)ep)[2 * e + 1]; }
        }
        const float* xa = x + (size_t)ia * 256;
        const float* xb = x + (size_t)ib * 256;
        const int k0 = sub * 32;
        #pragma unroll
        for (int j = 0; j < 4; j++) {
            const int k = k0 + 8 * j;
            float4 a0 = __ldg((const float4*)(xa + k));
            float4 a1 = __ldg((const float4*)(xa + k + 4));
            float4 c0 = __ldg((const float4*)(xb + k));
            float4 c1 = __ldg((const float4*)(xb + k + 4));
            union { __half2 h; uint32_t u; } q0, q1, q2, q3;
            q0.h = __floats2half2_rn(a0.x * c0.x, a0.y * c0.y);
            q1.h = __floats2half2_rn(a0.z * c0.z, a0.w * c0.w);
            q2.h = __floats2half2_rn(a1.x * c1.x, a1.y * c1.y);
            q3.h = __floats2half2_rn(a1.z * c1.z, a1.w * c1.w);
            *(uint4*)(smem + OFF_F + timg(p, k)) = make_uint4(q0.u, q1.u, q2.u, q3.u);
        }
    }

    // warp geometry
    const int wm = w & 1, wn = w >> 1;                  // L1: 2m x 8n (warp 32x32)
    const int arow0 = ((lane >> 3) & 1) * 8 + (lane & 7);
    const int acsel = lane >> 4;
    const int brow0 = ((lane >> 4) & 1) * 8 + (lane & 7);
    const int bcsel = (lane >> 3) & 1;
    const uint32_t aB = sb + OFF_F;

    CP_WAIT(1);            // W1 slice0 landed
    __syncthreads();       // + feats + b1 staged

    // ================= layer 1: 64x256x256, warp 32x32 =================
    float acc1[2][4][4];
    #pragma unroll
    for (int mi = 0; mi < 2; mi++)
        #pragma unroll
        for (int ni = 0; ni < 4; ni++)
            #pragma unroll
            for (int v = 0; v < 4; v++) acc1[mi][ni][v] = 0.0f;

    #pragma unroll
    for (int s = 0; s < 8; s++) {
        const uint32_t bB = sb + ((s & 1) ? OFF_WS1 : OFF_WS0);
        #pragma unroll
        for (int ksl = 0; ksl < 2; ksl++) {
            const int ks = 2 * s + ksl;
            uint32_t af[2][4];
            #pragma unroll
            for (int mi = 0; mi < 2; mi++) {
                const int r = wm * 32 + mi * 16 + arow0;
                ldsm_x4(af[mi], aB + r * 512 + ((((2 * ks + acsel) ^ (r & 7)) & 31) << 4));
            }
            #pragma unroll
            for (int nb = 0; nb < 2; nb++) {
                const int r = wn * 32 + nb * 16 + brow0;
                const int kc = 2 * ksl + bcsel;
                uint32_t bf[4];
                ldsm_x4(bf, bB + r * 64 + (((kc ^ ((r >> 1) & 3)) & 3) << 4));
                #pragma unroll
                for (int mi = 0; mi < 2; mi++) {
                    mma16816(acc1[mi][nb * 2 + 0], af[mi], bf[0], bf[1]);
                    mma16816(acc1[mi][nb * 2 + 1], af[mi], bf[2], bf[3]);
                }
            }
        }
        __syncthreads();                  // all warps done reading buf (s&1)
        {
            const int rs = s + 2;
            const uint32_t bufOff = (s & 1) ? OFF_WS1 : OFF_WS0;
            if (rs < 8) {                 // next W1 slice
                CP16(sb + bufOff + tid * 16, g_W1s + rs * 16384 + tid * 16);
                CP16(sb + bufOff + (tid + 512) * 16, g_W1s + rs * 16384 + (tid + 512) * 16);
            } else {                      // W2 slice rs-8 (0 or 1)
                CP16(sb + bufOff + tid * 16, g_W2s + (rs - 8) * 16384 + tid * 16);
                CP16(sb + bufOff + (tid + 512) * 16, g_W2s + (rs - 8) * 16384 + (tid + 512) * 16);
            }
        }
        CP_COMMIT();
        CP_WAIT(1);                       // slice s+1 resident
        __syncthreads();
    }

    // ---- epilogue 1: h1 = fp16(relu(acc1 + b1)) -> feats buffer ----
    #pragma unroll
    for (int mi = 0; mi < 2; mi++) {
        const int r0 = wm * 32 + mi * 16 + g, r1 = r0 + 8;
        #pragma unroll
        for (int ni = 0; ni < 4; ni++) {
            const int c0 = wn * 32 + ni * 8 + 2 * tig;
            const float2 bb = *(const float2*)&sB1[c0];
            union { __half2 h; uint32_t u; } lo, hi;
            lo.h = __floats2half2_rn(fmaxf(acc1[mi][ni][0] + bb.x, 0.0f),
                                     fmaxf(acc1[mi][ni][1] + bb.y, 0.0f));
            hi.h = __floats2half2_rn(fmaxf(acc1[mi][ni][2] + bb.x, 0.0f),
                                     fmaxf(acc1[mi][ni][3] + bb.y, 0.0f));
            *(uint32_t*)(smem + OFF_F + timg(r0, c0)) = lo.u;
            *(uint32_t*)(smem + OFF_F + timg(r1, c0)) = hi.u;
        }
    }
    __syncthreads();       // h1 visible

    // ================= layer 2: 64x128x256, warp 32x16 =================
    const int wm2 = w & 1, wn2 = w >> 1;               // 2m x 8n (warp 32x16)
    float acc2[2][2][4];
    #pragma unroll
    for (int mi = 0; mi < 2; mi++)
        #pragma unroll
        for (int nb = 0; nb < 2; nb++)
            #pragma unroll
            for (int v = 0; v < 4; v++) acc2[mi][nb][v] = 0.0f;

    #pragma unroll
    for (int s2 = 0; s2 < 4; s2++) {
        const uint32_t bB = sb + ((s2 & 1) ? OFF_WS1 : OFF_WS0);
        #pragma unroll
        for (int ksl = 0; ksl < 4; ksl++) {
            const int ks = 4 * s2 + ksl;
            uint32_t af[2][4];
            #pragma unroll
            for (int mi = 0; mi < 2; mi++) {
                const int r = wm2 * 32 + mi * 16 + arow0;
                ldsm_x4(af[mi], aB + r * 512 + ((((2 * ks + acsel) ^ (r & 7)) & 31) << 4));
            }
            const int r = wn2 * 16 + brow0;
            uint32_t bf[4];
            ldsm_x4(bf, bB + r * 128 + ((((2 * ksl + bcsel) ^ (r & 7)) & 7) << 4));
            #pragma unroll
            for (int mi = 0; mi < 2; mi++) {
                mma16816(acc2[mi][0], af[mi], bf[0], bf[1]);
                mma16816(acc2[mi][1], af[mi], bf[2], bf[3]);
            }
        }
        if (s2 < 2) {
            __syncthreads();              // readers of buf(s2&1) done
            const uint32_t bufOff = (s2 & 1) ? OFF_WS1 : OFF_WS0;
            CP16(sb + bufOff + tid * 16, g_W2s + (s2 + 2) * 16384 + tid * 16);
            CP16(sb + bufOff + (tid + 512) * 16, g_W2s + (s2 + 2) * 16384 + (tid + 512) * 16);
            CP_COMMIT();
            CP_WAIT(1);                   // slice s2+1 resident
            __syncthreads();
        } else if (s2 == 2) {
            CP_WAIT(0);                   // slice 3 resident
            __syncthreads();
        }
    }

    // ---- layer 3: out = relu(D2 + b2) . W3 + b3 ----
    {
        const int c0 = wn2 * 16 + 2 * tig;
        const float2 b2r0 = __ldg((const float2*)(b2 + c0));
        const float2 b2r1 = __ldg((const float2*)(b2 + c0 + 8));
        const float2 w3r0 = __ldg((const float2*)(W3 + c0));
        const float2 w3r1 = __ldg((const float2*)(W3 + c0 + 8));
        #pragma unroll
        for (int mi = 0; mi < 2; mi++) {
            float s0 = fmaxf(acc2[mi][0][0] + b2r0.x, 0.0f) * w3r0.x
                     + fmaxf(acc2[mi][0][1] + b2r0.y, 0.0f) * w3r0.y
                     + fmaxf(acc2[mi][1][0] + b2r1.x, 0.0f) * w3r1.x
                     + fmaxf(acc2[mi][1][1] + b2r1.y, 0.0f) * w3r1.y;
            float s1 = fmaxf(acc2[mi][0][2] + b2r0.x, 0.0f) * w3r0.x
                     + fmaxf(acc2[mi][0][3] + b2r0.y, 0.0f) * w3r0.y
                     + fmaxf(acc2[mi][1][2] + b2r1.x, 0.0f) * w3r1.x
                     + fmaxf(acc2[mi][1][3] + b2r1.y, 0.0f) * w3r1.y;
            s0 += __shfl_xor_sync(0xffffffffu, s0, 1);
            s0 += __shfl_xor_sync(0xffffffffu, s0, 2);
            s1 += __shfl_xor_sync(0xffffffffu, s1, 1);
            s1 += __shfl_xor_sync(0xffffffffu, s1, 2);
            if (tig == 0) {
                const int r0 = wm2 * 32 + mi * 16 + g;
                sPart[wn2 * 64 + r0]     = s0;
                sPart[wn2 * 64 + r0 + 8] = s1;
            }
        }
    }
    __syncthreads();

    if (tid < 64) {
        const long long e = e0 + tid;
        if (e < E) {
            float s = __ldg(b3);
            #pragma unroll
            for (int j = 0; j < 8; j++) s += sPart[j * 64 + tid];
            out[e] = s;
        }
    }
}

// ---------------------------------------------------------------------------
extern "C" void kernel_launch(void* const* d_in, const int* in_sizes, int n_in,
                              void* d_out, int out_size)
{
    const float* x  = (const float*)d_in[0];
    const float* W1 = (const float*)d_in[1];
    const float* b1 = (const float*)d_in[2];
    const float* W2 = (const float*)d_in[3];
    const float* b2 = (const float*)d_in[4];
    const float* W3 = (const float*)d_in[5];
    const float* b3 = (const float*)d_in[6];
    // d_in[7] = edge_index (unused)
    const void*  ep = d_in[8];
    float* out = (float*)d_out;

    const int E = out_size;
    prep_kernel<<<256, 256>>>(W1, W2);

    cudaFuncSetAttribute(pairmlp_occ_kernel,
                         cudaFuncAttributeMaxDynamicSharedMemorySize, SMEM_BYTES);
    const int nblocks = (E + TILE - 1) / TILE;
    pairmlp_occ_kernel<<<nblocks, NTH, SMEM_BYTES>>>(x, b1, b2, W3, b3, ep, out, E);
}

// round 11
// speedup vs baseline: 1.4607x; 1.1099x over previous
#include <cuda_runtime.h>
#include <cuda_fp16.h>
#include <cstdint>

// ============================================================================
// PairwiseMLPLinkPredictor — HMMA with LDG fragment weights (no weight smem).
//   2 CTAs/SM x 512 threads, TILE=64 pairs/CTA, 64 regs.
//   W1/W2 stored as pre-packed mma B-fragment images in global memory
//   (prep kernel). Kernel reads them with coalesced LDG.128 -> L1D-cached,
//   shared across both CTAs on the SM. smem holds only feats (32KB) + misc.
//   Fragment packing replicates EXACTLY what ldmatrix delivered in R10.
// ============================================================================

#define NTH    512
#define TILE   64

// ---- SMEM layout (bytes), 35840 per CTA -> 2 CTAs/SM, big L1D carveout ----
#define OFF_F     0        // 32768 : feats/h1 [64][256] f16 swizzled (512B rows)
#define OFF_B1    32768    // 1024
#define OFF_PART  33792    // 2048  : [8 ngroups][64 rows]
#define SMEM_BYTES 35840

// feats tile [rows][256] f16, 512B rows, 32 x 16B chunks, XOR-(r&7) swizzle
__host__ __device__ __forceinline__ uint32_t timg(int r, int k) {
    return (uint32_t)(r * 512 + ((((k >> 3) ^ (r & 7)) & 31) << 4) + ((k & 7) << 1));
}

// ---- fragment-ordered weight images ----
// W1f: [ks 16][nblk 16][lane 32] x uint4   (131072 B)
// W2f: [ks 16][nblk  8][lane 32] x uint4   ( 65536 B)
// uint4 = (b0, b1, b0', b1') for the two 8-col halves of a 16-col n-block,
// packed identically to ldmatrix.x4 output in the R10 kernel.
__device__ __align__(1024) unsigned char g_W1f[131072];
__device__ __align__(1024) unsigned char g_W2f[65536];

// ---------------------------------------------------------------------------
__device__ __forceinline__ uint32_t smem_u32(const void* p) {
    uint32_t a;
    asm("{ .reg .u64 t; cvta.to.shared.u64 t, %1; cvt.u32.u64 %0, t; }" : "=r"(a) : "l"(p));
    return a;
}
__device__ __forceinline__ void ldsm_x4(uint32_t r[4], uint32_t addr) {
    asm volatile("ldmatrix.sync.aligned.m8n8.x4.shared.b16 {%0,%1,%2,%3}, [%4];"
                 : "=r"(r[0]), "=r"(r[1]), "=r"(r[2]), "=r"(r[3]) : "r"(addr));
}
__device__ __forceinline__ void mma16816(float c[4], const uint32_t a[4],
                                         uint32_t b0, uint32_t b1) {
    asm volatile("mma.sync.aligned.m16n8k16.row.col.f32.f16.f16.f32 "
                 "{%0,%1,%2,%3}, {%4,%5,%6,%7}, {%8,%9}, {%0,%1,%2,%3};"
                 : "+f"(c[0]), "+f"(c[1]), "+f"(c[2]), "+f"(c[3])
                 : "r"(a[0]), "r"(a[1]), "r"(a[2]), "r"(a[3]), "r"(b0), "r"(b1));
}

// ---------------------------------------------------------------------------
// Prep: build fragment images.
// R10's ldmatrix delivered, for n-block base n0 and k base k0=16*ks, lane l:
//   bf[0] = half2( B[n0 +   l/4][k0 + 2*(l&3)],  B[n0 +   l/4][k0 + 2*(l&3)+1] )
//   bf[1] = same rows, k0+8
//   bf[2] = half2( B[n0+8+ l/4][k0 + 2*(l&3)],  ... )
//   bf[3] = same rows, k0+8
// with B[n][k] = W[k*N + n]  (W row-major [K][N] as given by the model).
// ---------------------------------------------------------------------------
__device__ __forceinline__ uint32_t pack_h2(float lo, float hi) {
    union { __half2 h; uint32_t u; } p;
    p.h = __floats2half2_rn(lo, hi);
    return p.u;
}
__global__ void prep_kernel(const float* __restrict__ W1, const float* __restrict__ W2) {
    const int i = blockIdx.x * blockDim.x + threadIdx.x;   // 8192 threads used
    if (i < 8192) {   // W1 frags: ks = i>>9, nblk = (i>>5)&15, lane = i&31
        const int ks = i >> 9, nblk = (i >> 5) & 15, l = i & 31;
        const int k0 = ks * 16 + 2 * (l & 3);
        const int n0 = nblk * 16 + (l >> 2);
        uint4 v;
        v.x = pack_h2(W1[(k0)     * 256 + n0],     W1[(k0 + 1) * 256 + n0]);
        v.y = pack_h2(W1[(k0 + 8) * 256 + n0],     W1[(k0 + 9) * 256 + n0]);
        v.z = pack_h2(W1[(k0)     * 256 + n0 + 8], W1[(k0 + 1) * 256 + n0 + 8]);
        v.w = pack_h2(W1[(k0 + 8) * 256 + n0 + 8], W1[(k0 + 9) * 256 + n0 + 8]);
        *(uint4*)(g_W1f + (size_t)i * 16) = v;
    }
    if (i < 4096) {   // W2 frags: ks = i>>8, nblk = (i>>5)&7, lane = i&31
        const int ks = i >> 8, nblk = (i >> 5) & 7, l = i & 31;
        const int k0 = ks * 16 + 2 * (l & 3);
        const int n0 = nblk * 16 + (l >> 2);
        uint4 v;
        v.x = pack_h2(W2[(k0)     * 128 + n0],     W2[(k0 + 1) * 128 + n0]);
        v.y = pack_h2(W2[(k0 + 8) * 128 + n0],     W2[(k0 + 9) * 128 + n0]);
        v.z = pack_h2(W2[(k0)     * 128 + n0 + 8], W2[(k0 + 1) * 128 + n0 + 8]);
        v.w = pack_h2(W2[(k0 + 8) * 128 + n0 + 8], W2[(k0 + 9) * 128 + n0 + 8]);
        *(uint4*)(g_W2f + (size_t)i * 16) = v;
    }
}

// ---------------------------------------------------------------------------
__global__ void __launch_bounds__(NTH, 2)
pairmlp_ldg_kernel(const float* __restrict__ x,
                   const float* __restrict__ b1, const float* __restrict__ b2,
                   const float* __restrict__ W3, const float* __restrict__ b3,
                   const void*  __restrict__ ep, float* __restrict__ out, int E)
{
    extern __shared__ char smem[];
    const uint32_t sb = smem_u32(smem);
    const int tid = threadIdx.x, w = tid >> 5, lane = tid & 31;
    const int g = lane >> 2, tig = lane & 3;
    const long long e0 = (long long)blockIdx.x * TILE;

    float* sB1 = (float*)(smem + OFF_B1);
    float* sPart = (float*)(smem + OFF_PART);

    // ---- dtype probe: int64 edge_pairs -> odd int32 words of first 1KB all 0 ----
    int probe = 0;
    if (tid < 128) probe = ((const int*)ep)[2 * tid + 1];
    const bool is32 = (__syncthreads_or(probe != 0) != 0);

    if (tid < 256) sB1[tid] = b1[tid];

    // ---- gather + product -> fp16 feats (8 threads per pair) ----
    {
        const int p = tid >> 3, sub = tid & 7;
        const long long e = e0 + p;
        long long ia = 0, ib = 0;
        if (e < (long long)E) {
            if (is32) { ia = ((const int*)ep)[2 * e];       ib = ((const int*)ep)[2 * e + 1]; }
            else      { ia = ((const long long*)ep)[2 * e]; ib = ((const long long*)ep)[2 * e + 1]; }
        }
        const float* xa = x + (size_t)ia * 256;
        const float* xb = x + (size_t)ib * 256;
        const int k0 = sub * 32;
        #pragma unroll
        for (int j = 0; j < 4; j++) {
            const int k = k0 + 8 * j;
            float4 a0 = __ldg((const float4*)(xa + k));
            float4 a1 = __ldg((const float4*)(xa + k + 4));
            float4 c0 = __ldg((const float4*)(xb + k));
            float4 c1 = __ldg((const float4*)(xb + k + 4));
            union { __half2 h; uint32_t u; } q0, q1, q2, q3;
            q0.h = __floats2half2_rn(a0.x * c0.x, a0.y * c0.y);
            q1.h = __floats2half2_rn(a0.z * c0.z, a0.w * c0.w);
            q2.h = __floats2half2_rn(a1.x * c1.x, a1.y * c1.y);
            q3.h = __floats2half2_rn(a1.z * c1.z, a1.w * c1.w);
            *(uint4*)(smem + OFF_F + timg(p, k)) = make_uint4(q0.u, q1.u, q2.u, q3.u);
        }
    }

    // warp geometry (identical to R10)
    const int wm = w & 1, wn = w >> 1;                  // L1: 2m x 8n (warp 32x32)
    const int arow0 = ((lane >> 3) & 1) * 8 + (lane & 7);
    const int acsel = lane >> 4;
    const uint32_t aB = sb + OFF_F;

    __syncthreads();       // feats + b1 staged

    // ================= layer 1: 64x256x256, warp 32x32, B via LDG ============
    float acc1[2][4][4];
    #pragma unroll
    for (int mi = 0; mi < 2; mi++)
        #pragma unroll
        for (int ni = 0; ni < 4; ni++)
            #pragma unroll
            for (int v = 0; v < 4; v++) acc1[mi][ni][v] = 0.0f;

    {
        // this warp's fragment stream: nblk 2wn and 2wn+1, all 16 ks
        const uint4* f0 = (const uint4*)(g_W1f) + ((size_t)(2 * wn) * 32 + lane);
        #pragma unroll
        for (int ks = 0; ks < 16; ks++) {
            uint32_t af[2][4];
            #pragma unroll
            for (int mi = 0; mi < 2; mi++) {
                const int r = wm * 32 + mi * 16 + arow0;
                ldsm_x4(af[mi], aB + r * 512 + ((((2 * ks + acsel) ^ (r & 7)) & 31) << 4));
            }
            #pragma unroll
            for (int nb = 0; nb < 2; nb++) {
                const uint4 bv = __ldg(f0 + ((size_t)ks * 16 + nb) * 32);
                #pragma unroll
                for (int mi = 0; mi < 2; mi++) {
                    mma16816(acc1[mi][nb * 2 + 0], af[mi], bv.x, bv.y);
                    mma16816(acc1[mi][nb * 2 + 1], af[mi], bv.z, bv.w);
                }
            }
        }
    }
    __syncthreads();       // all warps done reading feats

    // ---- epilogue 1: h1 = fp16(relu(acc1 + b1)) -> feats buffer ----
    #pragma unroll
    for (int mi = 0; mi < 2; mi++) {
        const int r0 = wm * 32 + mi * 16 + g, r1 = r0 + 8;
        #pragma unroll
        for (int ni = 0; ni < 4; ni++) {
            const int c0 = wn * 32 + ni * 8 + 2 * tig;
            const float2 bb = *(const float2*)&sB1[c0];
            union { __half2 h; uint32_t u; } lo, hi;
            lo.h = __floats2half2_rn(fmaxf(acc1[mi][ni][0] + bb.x, 0.0f),
                                     fmaxf(acc1[mi][ni][1] + bb.y, 0.0f));
            hi.h = __floats2half2_rn(fmaxf(acc1[mi][ni][2] + bb.x, 0.0f),
                                     fmaxf(acc1[mi][ni][3] + bb.y, 0.0f));
            *(uint32_t*)(smem + OFF_F + timg(r0, c0)) = lo.u;
            *(uint32_t*)(smem + OFF_F + timg(r1, c0)) = hi.u;
        }
    }
    __syncthreads();       // h1 visible

    // ================= layer 2: 64x128x256, warp 32x16, B via LDG ============
    const int wm2 = w & 1, wn2 = w >> 1;               // 2m x 8n
    float acc2[2][2][4];
    #pragma unroll
    for (int mi = 0; mi < 2; mi++)
        #pragma unroll
        for (int nb = 0; nb < 2; nb++)
            #pragma unroll
            for (int v = 0; v < 4; v++) acc2[mi][nb][v] = 0.0f;

    {
        const uint4* f2 = (const uint4*)(g_W2f) + ((size_t)wn2 * 32 + lane);
        #pragma unroll
        for (int ks = 0; ks < 16; ks++) {
            uint32_t af[2][4];
            #pragma unroll
            for (int mi = 0; mi < 2; mi++) {
                const int r = wm2 * 32 + mi * 16 + arow0;
                ldsm_x4(af[mi], aB + r * 512 + ((((2 * ks + acsel) ^ (r & 7)) & 31) << 4));
            }
            const uint4 bv = __ldg(f2 + (size_t)ks * 8 * 32);
            #pragma unroll
            for (int mi = 0; mi < 2; mi++) {
                mma16816(acc2[mi][0], af[mi], bv.x, bv.y);
                mma16816(acc2[mi][1], af[mi], bv.z, bv.w);
            }
        }
    }

    // ---- layer 3: out = relu(D2 + b2) . W3 + b3 (R10-validated geometry) ----
    {
        const int c0 = wn2 * 16 + 2 * tig;
        const float2 b2r0 = __ldg((const float2*)(b2 + c0));
        const float2 b2r1 = __ldg((const float2*)(b2 + c0 + 8));
        const float2 w3r0 = __ldg((const float2*)(W3 + c0));
        const float2 w3r1 = __ldg((const float2*)(W3 + c0 + 8));
        #pragma unroll
        for (int mi = 0; mi < 2; mi++) {
            float s0 = fmaxf(acc2[mi][0][0] + b2r0.x, 0.0f) * w3r0.x
                     + fmaxf(acc2[mi][0][1] + b2r0.y, 0.0f) * w3r0.y
                     + fmaxf(acc2[mi][1][0] + b2r1.x, 0.0f) * w3r1.x
                     + fmaxf(acc2[mi][1][1] + b2r1.y, 0.0f) * w3r1.y;
            float s1 = fmaxf(acc2[mi][0][2] + b2r0.x, 0.0f) * w3r0.x
                     + fmaxf(acc2[mi][0][3] + b2r0.y, 0.0f) * w3r0.y
                     + fmaxf(acc2[mi][1][2] + b2r1.x, 0.0f) * w3r1.x
                     + fmaxf(acc2[mi][1][3] + b2r1.y, 0.0f) * w3r1.y;
            s0 += __shfl_xor_sync(0xffffffffu, s0, 1);
            s0 += __shfl_xor_sync(0xffffffffu, s0, 2);
            s1 += __shfl_xor_sync(0xffffffffu, s1, 1);
            s1 += __shfl_xor_sync(0xffffffffu, s1, 2);
            if (tig == 0) {
                const int r0 = wm2 * 32 + mi * 16 + g;
                sPart[wn2 * 64 + r0]     = s0;
                sPart[wn2 * 64 + r0 + 8] = s1;
            }
        }
    }
    __syncthreads();

    if (tid < 64) {
        const long long e = e0 + tid;
        if (e < E) {
            float s = __ldg(b3);
            #pragma unroll
            for (int j = 0; j < 8; j++) s += sPart[j * 64 + tid];
            out[e] = s;
        }
    }
}

// ---------------------------------------------------------------------------
extern "C" void kernel_launch(void* const* d_in, const int* in_sizes, int n_in,
                              void* d_out, int out_size)
{
    const float* x  = (const float*)d_in[0];
    const float* W1 = (const float*)d_in[1];
    const float* b1 = (const float*)d_in[2];
    const float* W2 = (const float*)d_in[3];
    const float* b2 = (const float*)d_in[4];
    const float* W3 = (const float*)d_in[5];
    const float* b3 = (const float*)d_in[6];
    // d_in[7] = edge_index (unused)
    const void*  ep = d_in[8];
    float* out = (float*)d_out;

    const int E = out_size;
    prep_kernel<<<32, 256>>>(W1, W2);

    cudaFuncSetAttribute(pairmlp_ldg_kernel,
                         cudaFuncAttributeMaxDynamicSharedMemorySize, SMEM_BYTES);
    const int nblocks = (E + TILE - 1) / TILE;
    pairmlp_ldg_kernel<<<nblocks, NTH, SMEM_BYTES>>>(x, b1, b2, W3, b3, ep, out, E);
}

// round 13
// speedup vs baseline: 2.3365x; 1.5996x over previous
#include <cuda_runtime.h>
#include <cuda_fp16.h>
#include <cstdint>

// ============================================================================
// PairwiseMLPLinkPredictor — HMMA + LDG fragment weights, coalesced gather.
//   2 CTAs/SM x 512 threads, TILE=64 pairs/CTA, 64 regs.
//   W1/W2 as pre-packed mma B-fragment images in global (L1D-cached LDG.128).
//   Gather remapped so each warp's loads are contiguous 256B spans per pair.
//   dtype probe hoisted into prep kernel (g_is32 flag).
// ============================================================================

#define NTH    512
#define TILE   64

// ---- SMEM layout (bytes), 35840 per CTA -> 2 CTAs/SM, big L1D carveout ----
#define OFF_F     0        // 32768 : feats/h1 [64][256] f16 swizzled (512B rows)
#define OFF_B1    32768    // 1024
#define OFF_PART  33792    // 2048  : [8 ngroups][64 rows]
#define SMEM_BYTES 35840

// feats tile [rows][256] f16, 512B rows, 32 x 16B chunks, XOR-(r&7) swizzle
__host__ __device__ __forceinline__ uint32_t timg(int r, int k) {
    return (uint32_t)(r * 512 + ((((k >> 3) ^ (r & 7)) & 31) << 4) + ((k & 7) << 1));
}

// ---- fragment-ordered weight images (R11-validated packing) ----
__device__ __align__(1024) unsigned char g_W1f[131072]; // [ks16][nblk16][lane32] uint4
__device__ __align__(1024) unsigned char g_W2f[65536];  // [ks16][nblk 8][lane32] uint4
__device__ int g_is32;                                  // edge_pairs dtype flag

// ---------------------------------------------------------------------------
__device__ __forceinline__ uint32_t smem_u32(const void* p) {
    uint32_t a;
    asm("{ .reg .u64 t; cvta.to.shared.u64 t, %1; cvt.u32.u64 %0, t; }" : "=r"(a) : "l"(p));
    return a;
}
__device__ __forceinline__ void ldsm_x4(uint32_t r[4], uint32_t addr) {
    asm volatile("ldmatrix.sync.aligned.m8n8.x4.shared.b16 {%0,%1,%2,%3}, [%4];"
                 : "=r"(r[0]), "=r"(r[1]), "=r"(r[2]), "=r"(r[3]) : "r"(addr));
}
__device__ __forceinline__ void mma16816(float c[4], const uint32_t a[4],
                                         uint32_t b0, uint32_t b1) {
    asm volatile("mma.sync.aligned.m16n8k16.row.col.f32.f16.f16.f32 "
                 "{%0,%1,%2,%3}, {%4,%5,%6,%7}, {%8,%9}, {%0,%1,%2,%3};"
                 : "+f"(c[0]), "+f"(c[1]), "+f"(c[2]), "+f"(c[3])
                 : "r"(a[0]), "r"(a[1]), "r"(a[2]), "r"(a[3]), "r"(b0), "r"(b1));
}
__device__ __forceinline__ uint32_t pack_h2(float lo, float hi) {
    union { __half2 h; uint32_t u; } p;
    p.h = __floats2half2_rn(lo, hi);
    return p.u;
}

// ---------------------------------------------------------------------------
// Prep: build fragment images + dtype flag.
// Fragment packing identical to R11 (ldmatrix-equivalent, validated).
// ---------------------------------------------------------------------------
__global__ void prep_kernel(const float* __restrict__ W1, const float* __restrict__ W2,
                            const void* __restrict__ ep) {
    const int i = blockIdx.x * blockDim.x + threadIdx.x;
    if (i < 8192) {   // W1 frags
        const int ks = i >> 9, nblk = (i >> 5) & 15, l = i & 31;
        const int k0 = ks * 16 + 2 * (l & 3);
        const int n0 = nblk * 16 + (l >> 2);
        uint4 v;
        v.x = pack_h2(W1[(k0)     * 256 + n0],     W1[(k0 + 1) * 256 + n0]);
        v.y = pack_h2(W1[(k0 + 8) * 256 + n0],     W1[(k0 + 9) * 256 + n0]);
        v.z = pack_h2(W1[(k0)     * 256 + n0 + 8], W1[(k0 + 1) * 256 + n0 + 8]);
        v.w = pack_h2(W1[(k0 + 8) * 256 + n0 + 8], W1[(k0 + 9) * 256 + n0 + 8]);
        *(uint4*)(g_W1f + (size_t)i * 16) = v;
    }
    if (i < 4096) {   // W2 frags
        const int ks = i >> 8, nblk = (i >> 5) & 7, l = i & 31;
        const int k0 = ks * 16 + 2 * (l & 3);
        const int n0 = nblk * 16 + (l >> 2);
        uint4 v;
        v.x = pack_h2(W2[(k0)     * 128 + n0],     W2[(k0 + 1) * 128 + n0]);
        v.y = pack_h2(W2[(k0 + 8) * 128 + n0],     W2[(k0 + 9) * 128 + n0]);
        v.z = pack_h2(W2[(k0)     * 128 + n0 + 8], W2[(k0 + 1) * 128 + n0 + 8]);
        v.w = pack_h2(W2[(k0 + 8) * 128 + n0 + 8], W2[(k0 + 9) * 128 + n0 + 8]);
        *(uint4*)(g_W2f + (size_t)i * 16) = v;
    }
    // dtype probe: int64 edge_pairs -> odd int32 words of first 1KB all zero
    if (blockIdx.x == 0 && threadIdx.x < 128) {
        const int v = ((const int*)ep)[2 * threadIdx.x + 1];
        const int any = __syncthreads_or(v != 0);
        if (threadIdx.x == 0) g_is32 = any;
    }
}

// ---------------------------------------------------------------------------
__global__ void __launch_bounds__(NTH, 2)
pairmlp_ldg_kernel(const float* __restrict__ x,
                   const float* __restrict__ b1, const float* __restrict__ b2,
                   const float* __restrict__ W3, const float* __restrict__ b3,
                   const void*  __restrict__ ep, float* __restrict__ out, int E)
{
    extern __shared__ char smem[];
    const uint32_t sb = smem_u32(smem);
    const int tid = threadIdx.x, w = tid >> 5, lane = tid & 31;
    const int g = lane >> 2, tig = lane & 3;
    const long long e0 = (long long)blockIdx.x * TILE;

    float* sB1 = (float*)(smem + OFF_B1);
    float* sPart = (float*)(smem + OFF_PART);

    const bool is32 = (g_is32 != 0);
    if (tid < 256) sB1[tid] = b1[tid];

    // ---- gather + product -> fp16 feats (coalesced: 256B spans per pair) ----
    {
        const int p = tid >> 3, sub = tid & 7;
        const long long e = e0 + p;
        long long ia = 0, ib = 0;
        if (e < (long long)E) {
            if (is32) { ia = ((const int*)ep)[2 * e];       ib = ((const int*)ep)[2 * e + 1]; }
            else      { ia = ((const long long*)ep)[2 * e]; ib = ((const long long*)ep)[2 * e + 1]; }
        }
        const float* xa = x + (size_t)ia * 256;
        const float* xb = x + (size_t)ib * 256;
        #pragma unroll
        for (int jj = 0; jj < 8; jj++) {
            const int k = jj * 32 + sub * 4;         // 8 lanes -> contiguous 256B
            float4 a = __ldg((const float4*)(xa + k));
            float4 b = __ldg((const float4*)(xb + k));
            union { __half2 h; uint32_t u; } q0, q1;
            q0.h = __floats2half2_rn(a.x * b.x, a.y * b.y);
            q1.h = __floats2half2_rn(a.z * b.z, a.w * b.w);
            *(uint2*)(smem + OFF_F + timg(p, k)) = make_uint2(q0.u, q1.u);
        }
    }

    // warp geometry (R10/R11-validated)
    const int wm = w & 1, wn = w >> 1;                  // L1: 2m x 8n (warp 32x32)
    const int arow0 = ((lane >> 3) & 1) * 8 + (lane & 7);
    const int acsel = lane >> 4;
    const uint32_t aB = sb + OFF_F;

    __syncthreads();       // feats + b1 staged

    // ================= layer 1: 64x256x256, warp 32x32, B via LDG ============
    float acc1[2][4][4];
    #pragma unroll
    for (int mi = 0; mi < 2; mi++)
        #pragma unroll
        for (int ni = 0; ni < 4; ni++)
            #pragma unroll
            for (int v = 0; v < 4; v++) acc1[mi][ni][v] = 0.0f;

    {
        const uint4* f0 = (const uint4*)(g_W1f) + ((size_t)(2 * wn) * 32 + lane);
        #pragma unroll
        for (int ks = 0; ks < 16; ks++) {
            uint32_t af[2][4];
            #pragma unroll
            for (int mi = 0; mi < 2; mi++) {
                const int r = wm * 32 + mi * 16 + arow0;
                ldsm_x4(af[mi], aB + r * 512 + ((((2 * ks + acsel) ^ (r & 7)) & 31) << 4));
            }
            #pragma unroll
            for (int nb = 0; nb < 2; nb++) {
                const uint4 bv = __ldg(f0 + ((size_t)ks * 16 + nb) * 32);
                #pragma unroll
                for (int mi = 0; mi < 2; mi++) {
                    mma16816(acc1[mi][nb * 2 + 0], af[mi], bv.x, bv.y);
                    mma16816(acc1[mi][nb * 2 + 1], af[mi], bv.z, bv.w);
                }
            }
        }
    }
    __syncthreads();       // all warps done reading feats

    // ---- epilogue 1: h1 = fp16(relu(acc1 + b1)) -> feats buffer ----
    #pragma unroll
    for (int mi = 0; mi < 2; mi++) {
        const int r0 = wm * 32 + mi * 16 + g, r1 = r0 + 8;
        #pragma unroll
        for (int ni = 0; ni < 4; ni++) {
            const int c0 = wn * 32 + ni * 8 + 2 * tig;
            const float2 bb = *(const float2*)&sB1[c0];
            union { __half2 h; uint32_t u; } lo, hi;
            lo.h = __floats2half2_rn(fmaxf(acc1[mi][ni][0] + bb.x, 0.0f),
                                     fmaxf(acc1[mi][ni][1] + bb.y, 0.0f));
            hi.h = __floats2half2_rn(fmaxf(acc1[mi][ni][2] + bb.x, 0.0f),
                                     fmaxf(acc1[mi][ni][3] + bb.y, 0.0f));
            *(uint32_t*)(smem + OFF_F + timg(r0, c0)) = lo.u;
            *(uint32_t*)(smem + OFF_F + timg(r1, c0)) = hi.u;
        }
    }
    __syncthreads();       // h1 visible

    // ================= layer 2: 64x128x256, warp 32x16, B via LDG ============
    const int wm2 = w & 1, wn2 = w >> 1;               // 2m x 8n
    float acc2[2][2][4];
    #pragma unroll
    for (int mi = 0; mi < 2; mi++)
        #pragma unroll
        for (int nb = 0; nb < 2; nb++)
            #pragma unroll
            for (int v = 0; v < 4; v++) acc2[mi][nb][v] = 0.0f;

    {
        const uint4* f2 = (const uint4*)(g_W2f) + ((size_t)wn2 * 32 + lane);
        #pragma unroll
        for (int ks = 0; ks < 16; ks++) {
            uint32_t af[2][4];
            #pragma unroll
            for (int mi = 0; mi < 2; mi++) {
                const int r = wm2 * 32 + mi * 16 + arow0;
                ldsm_x4(af[mi], aB + r * 512 + ((((2 * ks + acsel) ^ (r & 7)) & 31) << 4));
            }
            const uint4 bv = __ldg(f2 + (size_t)ks * 8 * 32);
            #pragma unroll
            for (int mi = 0; mi < 2; mi++) {
                mma16816(acc2[mi][0], af[mi], bv.x, bv.y);
                mma16816(acc2[mi][1], af[mi], bv.z, bv.w);
            }
        }
    }

    // ---- layer 3: out = relu(D2 + b2) . W3 + b3 ----
    {
        const int c0 = wn2 * 16 + 2 * tig;
        const float2 b2r0 = __ldg((const float2*)(b2 + c0));
        const float2 b2r1 = __ldg((const float2*)(b2 + c0 + 8));
        const float2 w3r0 = __ldg((const float2*)(W3 + c0));
        const float2 w3r1 = __ldg((const float2*)(W3 + c0 + 8));
        #pragma unroll
        for (int mi = 0; mi < 2; mi++) {
            float s0 = fmaxf(acc2[mi][0][0] + b2r0.x, 0.0f) * w3r0.x
                     + fmaxf(acc2[mi][0][1] + b2r0.y, 0.0f) * w3r0.y
                     + fmaxf(acc2[mi][1][0] + b2r1.x, 0.0f) * w3r1.x
                     + fmaxf(acc2[mi][1][1] + b2r1.y, 0.0f) * w3r1.y;
            float s1 = fmaxf(acc2[mi][0][2] + b2r0.x, 0.0f) * w3r0.x
                     + fmaxf(acc2[mi][0][3] + b2r0.y, 0.0f) * w3r0.y
                     + fmaxf(acc2[mi][1][2] + b2r1.x, 0.0f) * w3r1.x
                     + fmaxf(acc2[mi][1][3] + b2r1.y, 0.0f) * w3r1.y;
            s0 += __shfl_xor_sync(0xffffffffu, s0, 1);
            s0 += __shfl_xor_sync(0xffffffffu, s0, 2);
            s1 += __shfl_xor_sync(0xffffffffu, s1, 1);
            s1 += __shfl_xor_sync(0xffffffffu, s1, 2);
            if (tig == 0) {
                const int r0 = wm2 * 32 + mi * 16 + g;
                sPart[wn2 * 64 + r0]     = s0;
                sPart[wn2 * 64 + r0 + 8] = s1;
            }
        }
    }
    __syncthreads();

    if (tid < 64) {
        const long long e = e0 + tid;
        if (e < E) {
            float s = __ldg(b3);
            #pragma unroll
            for (int j = 0; j < 8; j++) s += sPart[j * 64 + tid];
            out[e] = s;
        }
    }
}

// ---------------------------------------------------------------------------
extern "C" void kernel_launch(void* const* d_in, const int* in_sizes, int n_in,
                              void* d_out, int out_size)
{
    const float* x  = (const float*)d_in[0];
    const float* W1 = (const float*)d_in[1];
    const float* b1 = (const float*)d_in[2];
    const float* W2 = (const float*)d_in[3];
    const float* b2 = (const float*)d_in[4];
    const float* W3 = (const float*)d_in[5];
    const float* b3 = (const float*)d_in[6];
    // d_in[7] = edge_index (unused)
    const void*  ep = d_in[8];
    float* out = (float*)d_out;

    const int E = out_size;
    prep_kernel<<<32, 256>>>(W1, W2, ep);

    cudaFuncSetAttribute(pairmlp_ldg_kernel,
                         cudaFuncAttributeMaxDynamicSharedMemorySize, SMEM_BYTES);
    const int nblocks = (E + TILE - 1) / TILE;
    pairmlp_ldg_kernel<<<nblocks, NTH, SMEM_BYTES>>>(x, b1, b2, W3, b3, ep, out, E);
}